// round 6
// baseline (speedup 1.0000x reference)
#include <cuda_runtime.h>
#include <cuda_fp16.h>
#include <mma.h>
#include <cstdint>

using namespace nvcuda;

#define SEQ    512
#define INSZ   4096
#define HID    2048
#define OUTSZ  4096
#define STEPS  30
#define G3     6144   // 3*HID

#define NB     128    // persistent CTAs (1/SM, guaranteed co-resident)
#define NT     256
#define UPB    16     // hidden units per block   (2048/128)
#define RPB    48     // gate rows per block      (3*UPB)
#define ORPB   32     // output rows per block    (4096/128)

// ---------------- device globals (static scratch; no runtime allocation) ----
__device__ float               g_GI[SEQ * G3];        // Wih@x (NO bias)
__device__ __half              g_Xh[SEQ * INSZ];      // fp16 input
__device__ __half              g_Wh[G3 * INSZ];       // fp16 enc_Wih
__device__ float               g_h[2][HID];           // double-buffered hidden
__device__ unsigned            g_arrive[NB];
__device__ unsigned long long  g_amax[STEPS];
__device__ float               g_sumexp[STEPS];

// ---------------- helpers ---------------------------------------------------
__device__ __forceinline__ float warp_sum(float v) {
#pragma unroll
    for (int o = 16; o; o >>= 1) v += __shfl_xor_sync(0xffffffffu, v, o);
    return v;
}
__device__ __forceinline__ float sigmoidf_(float x) {
    return 1.0f / (1.0f + expf(-x));
}

// Single-stage grid barrier: every CTA bumps its flag, every CTA's warp 0
// polls all 128 flags directly (one L2 round trip on the critical path).
// Monotonic counters survive graph replays: all flags are equal at launch
// start, and `base` is captured before any flag can change.
__device__ __forceinline__ void grid_bar(int bid, unsigned base, unsigned* kbar) {
    unsigned k = ++(*kbar);
    __threadfence();              // release: prior global writes visible
    __syncthreads();
    if (threadIdx.x == 0) *(volatile unsigned*)&g_arrive[bid] = base + k;
    if (threadIdx.x < 32) {
        for (;;) {
            unsigned mn = 0xFFFFFFFFu;
#pragma unroll
            for (int i = 0; i < 4; i++) {
                unsigned d = (*(volatile unsigned*)&g_arrive[threadIdx.x + i * 32]) - base;
                mn = mn < d ? mn : d;
            }
            if (__all_sync(0xffffffffu, mn >= k)) break;
        }
    }
    __syncthreads();
    __threadfence();              // acquire side
}

// Load hidden state (written by other SMs) into shared memory, bypassing L1.
__device__ __forceinline__ void load_h(const float* hsrc, float* hs, int tid) {
#pragma unroll
    for (int i = 0; i < HID / (NT * 4); i++) {   // 2 iterations
        int idx = (tid + i * NT) * 4;
        float4 v = __ldcg((const float4*)(hsrc + idx));
        *(float4*)&hs[idx] = v;
    }
}

// One-time: load this CTA's 48 Whh rows (fp32, global) into SMEM as fp16.
// SMEM row r48 = gate*16 + j  <->  global row gate*HID + bid*16 + j.
__device__ void load_w48(const float* __restrict__ W, __half* ws, int bid, int tid) {
    int warp = tid >> 5, lane = tid & 31;
#pragma unroll
    for (int rr = 0; rr < 6; rr++) {
        int r48  = warp * 6 + rr;
        int grow = (r48 >> 4) * HID + bid * UPB + (r48 & 15);
        const float4* src = (const float4*)(W + (size_t)grow * HID);
#pragma unroll
        for (int c = 0; c < 16; c++) {
            float4 v = __ldg(&src[lane + c * 32]);
            union { __half2 h[2]; uint2 u; } cv;
            cv.h[0] = __floats2half2_rn(v.x, v.y);
            cv.h[1] = __floats2half2_rn(v.z, v.w);
            *(uint2*)&ws[(size_t)r48 * HID + (lane + c * 32) * 4] = cv.u;
        }
    }
}

// 48-row x 2048 matvec from SMEM fp16 weights, fp32 accumulation.
// Warp w handles rows w*6..w*6+5; result + bhh -> gh_s[48].
__device__ __forceinline__ void matvec48_smem(const __half* __restrict__ ws,
                                              const float* __restrict__ hs,
                                              float* gh_s, const float* bhh_s,
                                              int tid) {
    int warp = tid >> 5, lane = tid & 31;
    float acc[6] = {0.f, 0.f, 0.f, 0.f, 0.f, 0.f};
#pragma unroll
    for (int chunk = 0; chunk < 8; chunk++) {
        int col = (chunk * 32 + lane) * 8;          // half index
        float4 ha = *(const float4*)&hs[col];
        float4 hb = *(const float4*)&hs[col + 4];
#pragma unroll
        for (int rr = 0; rr < 6; rr++) {
            uint4 w = *(const uint4*)&ws[(size_t)(warp * 6 + rr) * HID + col];
            float2 f0 = __half22float2(*(const __half2*)&w.x);
            float2 f1 = __half22float2(*(const __half2*)&w.y);
            float2 f2 = __half22float2(*(const __half2*)&w.z);
            float2 f3 = __half22float2(*(const __half2*)&w.w);
            acc[rr] += f0.x * ha.x + f0.y * ha.y + f1.x * ha.z + f1.y * ha.w
                     + f2.x * hb.x + f2.y * hb.y + f3.x * hb.z + f3.y * hb.w;
        }
    }
#pragma unroll
    for (int rr = 0; rr < 6; rr++) {
        float s = warp_sum(acc[rr]);
        if (lane == 0) gh_s[warp * 6 + rr] = s + bhh_s[warp * 6 + rr];
    }
}

// ---------------- fp32 -> fp16 converters -----------------------------------
__global__ void __launch_bounds__(256) conv_x_kernel(const float* __restrict__ src) {
    int i = blockIdx.x * blockDim.x + threadIdx.x;   // float4 index
    if (i < SEQ * INSZ / 4) {
        float4 v = __ldg((const float4*)src + i);
        union { __half2 h[2]; uint2 u; } cv;
        cv.h[0] = __floats2half2_rn(v.x, v.y);
        cv.h[1] = __floats2half2_rn(v.z, v.w);
        ((uint2*)g_Xh)[i] = cv.u;
    }
}
__global__ void __launch_bounds__(256) conv_w_kernel(const float* __restrict__ src) {
    int i = blockIdx.x * blockDim.x + threadIdx.x;
    if (i < G3 * INSZ / 4) {
        float4 v = __ldg((const float4*)src + i);
        union { __half2 h[2]; uint2 u; } cv;
        cv.h[0] = __floats2half2_rn(v.x, v.y);
        cv.h[1] = __floats2half2_rn(v.z, v.w);
        ((uint2*)g_Wh)[i] = cv.u;
    }
}

// ---------------- kernel 1: GI = X @ Wih^T (tensor cores, fp32 accum) -------
// C[m,n] = sum_k Xh[m,k] * Wh[n,k];  M=512, N=6144, K=4096
#define KC 32
__global__ void __launch_bounds__(256) gemm_wmma_kernel() {
    __shared__ __half As[128][KC + 8];   // +8 halfs pad: ldm=40
    __shared__ __half Bs[128][KC + 8];

    int m0 = blockIdx.y * 128, n0 = blockIdx.x * 128;
    int t = threadIdx.x;
    int wid = t >> 5;
    int wm = wid & 1, wn = wid >> 1;     // warp tile: 64(M) x 32(N)

    wmma::fragment<wmma::accumulator, 16, 16, 16, float> c[4][2];
#pragma unroll
    for (int i = 0; i < 4; i++)
#pragma unroll
        for (int j = 0; j < 2; j++) wmma::fill_fragment(c[i][j], 0.f);

    int lrow = t >> 1;
    int lseg = (t & 1) * 16;             // half offset within KC

    for (int k0 = 0; k0 < INSZ; k0 += KC) {
        const uint4* ap = (const uint4*)(g_Xh + (size_t)(m0 + lrow) * INSZ + k0 + lseg);
        const uint4* bp = (const uint4*)(g_Wh + (size_t)(n0 + lrow) * INSZ + k0 + lseg);
        uint4 a0 = ap[0], a1 = ap[1];
        uint4 b0 = bp[0], b1 = bp[1];
        __syncthreads();
        *(uint4*)&As[lrow][lseg]     = a0;
        *(uint4*)&As[lrow][lseg + 8] = a1;
        *(uint4*)&Bs[lrow][lseg]     = b0;
        *(uint4*)&Bs[lrow][lseg + 8] = b1;
        __syncthreads();
#pragma unroll
        for (int kk = 0; kk < KC; kk += 16) {
            wmma::fragment<wmma::matrix_a, 16, 16, 16, __half, wmma::row_major> af[4];
            wmma::fragment<wmma::matrix_b, 16, 16, 16, __half, wmma::col_major> bf[2];
#pragma unroll
            for (int i = 0; i < 4; i++)
                wmma::load_matrix_sync(af[i], &As[wm * 64 + i * 16][kk], KC + 8);
#pragma unroll
            for (int j = 0; j < 2; j++)
                wmma::load_matrix_sync(bf[j], &Bs[wn * 32 + j * 16][kk], KC + 8);
#pragma unroll
            for (int i = 0; i < 4; i++)
#pragma unroll
                for (int j = 0; j < 2; j++)
                    wmma::mma_sync(c[i][j], af[i], bf[j], c[i][j]);
        }
    }
#pragma unroll
    for (int i = 0; i < 4; i++)
#pragma unroll
        for (int j = 0; j < 2; j++)
            wmma::store_matrix_sync(
                &g_GI[(size_t)(m0 + wm * 64 + i * 16) * G3 + n0 + wn * 32 + j * 16],
                c[i][j], G3, wmma::mem_row_major);
}

// ---------------- kernel 2: persistent encoder + decoder --------------------
__global__ void __launch_bounds__(NT, 1) rnn_kernel(
    const float* __restrict__ enc_Whh, const float* __restrict__ enc_bih,
    const float* __restrict__ enc_bhh,
    const float* __restrict__ dec_Wih, const float* __restrict__ dec_Whh,
    const float* __restrict__ dec_bih, const float* __restrict__ dec_bhh,
    const float* __restrict__ W_out,   const float* __restrict__ b_out,
    float* __restrict__ out) {

    extern __shared__ char dyn[];
    __half* ws = (__half*)dyn;                           // 48*2048 fp16 = 192KB
    float*  hs = (float*)(dyn + RPB * HID * sizeof(__half));  // 2048 f32 = 8KB

    __shared__ float gh_s[RPB];
    __shared__ float gi_s[RPB];
    __shared__ float bhh_s[RPB];
    __shared__ float bih_s[RPB];
    __shared__ float ls[ORPB];

    int bid = blockIdx.x, tid = threadIdx.x;
    unsigned base = *(volatile unsigned*)&g_arrive[bid];  // stable at launch
    unsigned kbar = 0;

    // one-time: encoder Whh slice -> SMEM fp16; biases -> SMEM
    load_w48(enc_Whh, ws, bid, tid);
    if (tid < RPB) {
        int grow = (tid >> 4) * HID + bid * UPB + (tid & 15);
        bhh_s[tid] = enc_bhh[grow];
        bih_s[tid] = enc_bih[grow];
    }

    // per-launch re-init
    if (tid < UPB) __stcg(&g_h[0][bid * UPB + tid], 0.f);
    if (bid == 0 && tid < STEPS) {
        g_amax[tid]   = 0ull;
        g_sumexp[tid] = 0.f;
    }
    grid_bar(bid, base, &kbar);

    int cur = 0;

    // ---------------- encoder: 512 sequential GRU steps ----------------
    for (int t = 0; t < SEQ; t++) {
        load_h(g_h[cur], hs, tid);
        __syncthreads();
        matvec48_smem(ws, hs, gh_s, bhh_s, tid);
        __syncthreads();
        if (tid < UPB) {
            int u = bid * UPB + tid;
            const float* gi = g_GI + (size_t)t * G3;
            float r = sigmoidf_(gi[u]           + bih_s[tid]      + gh_s[tid]);
            float z = sigmoidf_(gi[HID + u]     + bih_s[UPB + tid] + gh_s[UPB + tid]);
            float n = tanhf(    gi[2 * HID + u] + bih_s[2 * UPB + tid]
                                                + r * gh_s[2 * UPB + tid]);
            __stcg(&g_h[cur ^ 1][u], (1.f - z) * n + z * hs[u]);
        }
        cur ^= 1;
        grid_bar(bid, base, &kbar);
    }

    // ---------------- decoder: swap SMEM weights to dec_Whh ----------------
    load_w48(dec_Whh, ws, bid, tid);
    if (tid < RPB) {
        int grow = (tid >> 4) * HID + bid * UPB + (tid & 15);
        bhh_s[tid] = dec_bhh[grow];
    }
    __syncthreads();

    int prev_idx = -1;     // first x is the zero vector
    for (int s = 0; s < STEPS; s++) {
        load_h(g_h[cur], hs, tid);
        if (tid < RPB) {                       // gi = Wih[:,onehot] + bih
            int grow = (tid >> 4) * HID + bid * UPB + (tid & 15);
            float v = dec_bih[grow];
            if (prev_idx >= 0) v += __ldg(&dec_Wih[(size_t)grow * INSZ + prev_idx]);
            gi_s[tid] = v;
        }
        __syncthreads();
        matvec48_smem(ws, hs, gh_s, bhh_s, tid);
        __syncthreads();
        if (tid < UPB) {
            int u = bid * UPB + tid;
            float r = sigmoidf_(gi_s[tid]           + gh_s[tid]);
            float z = sigmoidf_(gi_s[UPB + tid]     + gh_s[UPB + tid]);
            float n = tanhf(    gi_s[2 * UPB + tid] + r * gh_s[2 * UPB + tid]);
            __stcg(&g_h[cur ^ 1][u], (1.f - z) * n + z * hs[u]);
        }
        cur ^= 1;
        grid_bar(bid, base, &kbar);           // B1: h_new visible everywhere

        // logits for this CTA's 32 output rows (fp32, streamed from L2)
        load_h(g_h[cur], hs, tid);
        __syncthreads();
        {
            int warp = tid >> 5, lane = tid & 31;
#pragma unroll
            for (int rr = 0; rr < 4; rr++) {
                int rl = warp * 4 + rr;
                int grow = bid * ORPB + rl;
                const float4* wrow = (const float4*)(W_out + (size_t)grow * HID);
                float acc = 0.f;
#pragma unroll
                for (int kk = 0; kk < 16; kk++) {
                    float4 w4 = __ldg(&wrow[lane + kk * 32]);
                    const float4 h4 = *(const float4*)&hs[(lane + kk * 32) * 4];
                    acc += w4.x * h4.x + w4.y * h4.y + w4.z * h4.z + w4.w * h4.w;
                }
                acc = warp_sum(acc);
                if (lane == 0) ls[rl] = acc + b_out[grow];
            }
        }
        __syncthreads();

        // global (max, argmax) via packed atomicMax; first-index tie-break
        if (tid < 32) {
            float v = ls[tid];
            unsigned sb = __float_as_uint(v);
            sb = (sb & 0x80000000u) ? ~sb : (sb | 0x80000000u);
            unsigned long long pack =
                ((unsigned long long)sb << 32) |
                (unsigned long long)(0xFFFFFFFFu - (unsigned)(bid * ORPB + tid));
#pragma unroll
            for (int o = 16; o; o >>= 1) {
                unsigned long long other = __shfl_xor_sync(0xffffffffu, pack, o);
                pack = other > pack ? other : pack;
            }
            if (tid == 0) atomicMax(&g_amax[s], pack);
        }
        grid_bar(bid, base, &kbar);           // B2: global max ready

        unsigned long long pk = *(volatile unsigned long long*)&g_amax[s];
        unsigned hi = (unsigned)(pk >> 32);
        float gmax = __uint_as_float((hi & 0x80000000u) ? (hi & 0x7FFFFFFFu) : ~hi);

        if (tid < 32) {
            float e = expf(ls[tid] - gmax);
            e = warp_sum(e);
            if (tid == 0) atomicAdd(&g_sumexp[s], e);
        }
        grid_bar(bid, base, &kbar);           // B3: global sumexp ready

        float lse = logf(*(volatile float*)&g_sumexp[s]);
        if (tid < 32)
            out[(size_t)s * OUTSZ + bid * ORPB + tid] = ls[tid] - gmax - lse;
        prev_idx = (int)(0xFFFFFFFFu - (unsigned)(pk & 0xFFFFFFFFull));
    }
}

// ---------------- launch ----------------------------------------------------
extern "C" void kernel_launch(void* const* d_in, const int* in_sizes, int n_in,
                              void* d_out, int out_size) {
    const float* input   = (const float*)d_in[0];
    const float* enc_Wih = (const float*)d_in[1];
    const float* enc_Whh = (const float*)d_in[2];
    const float* enc_bih = (const float*)d_in[3];
    const float* enc_bhh = (const float*)d_in[4];
    const float* dec_Wih = (const float*)d_in[5];
    const float* dec_Whh = (const float*)d_in[6];
    const float* dec_bih = (const float*)d_in[7];
    const float* dec_bhh = (const float*)d_in[8];
    const float* W_out   = (const float*)d_in[9];
    const float* b_out   = (const float*)d_in[10];
    float* out = (float*)d_out;

    static const int kDynSmem = RPB * HID * sizeof(__half) + HID * sizeof(float);
    cudaFuncSetAttribute(rnn_kernel,
                         cudaFuncAttributeMaxDynamicSharedMemorySize, kDynSmem);

    conv_x_kernel<<<(SEQ * INSZ / 4 + 255) / 256, 256>>>(input);
    conv_w_kernel<<<(G3 * INSZ / 4 + 255) / 256, 256>>>(enc_Wih);

    dim3 g1(G3 / 128, SEQ / 128);   // 48 x 4
    gemm_wmma_kernel<<<g1, 256>>>();

    rnn_kernel<<<NB, NT, kDynSmem>>>(enc_Whh, enc_bih, enc_bhh,
                                     dec_Wih, dec_Whh, dec_bih, dec_bhh,
                                     W_out, b_out, out);
}

// round 9
// speedup vs baseline: 1.3610x; 1.3610x over previous
#include <cuda_runtime.h>
#include <cuda_fp16.h>
#include <mma.h>
#include <cstdint>

using namespace nvcuda;

#define SEQ    512
#define INSZ   4096
#define HID    2048
#define OUTSZ  4096
#define STEPS  30
#define G3     6144   // 3*HID

#define NB     128    // persistent CTAs (1/SM, guaranteed co-resident)
#define NT     512    // 16 warps
#define NW     16
#define UPB    16     // hidden units per block   (2048/128)
#define RPB    48     // gate rows per block      (3*UPB)
#define RPW    3      // rows per warp            (48/16)
#define ORPB   32     // output rows per block    (4096/128)
#define ORPW   2      // output rows per warp

// ---------------- device globals (static scratch; no runtime allocation) ----
__device__ float               g_GI[SEQ * G3];        // Wih@x (NO bias)
__device__ __half              g_Xh[SEQ * INSZ];      // fp16 input
__device__ __half              g_Wh[G3 * INSZ];       // fp16 enc_Wih
__device__ float               g_h[2][HID];           // double-buffered hidden
__device__ unsigned            g_arrive[NB];
__device__ unsigned long long  g_amax[STEPS];
__device__ float               g_sumexp[STEPS];

// ---------------- helpers ---------------------------------------------------
__device__ __forceinline__ float warp_sum(float v) {
#pragma unroll
    for (int o = 16; o; o >>= 1) v += __shfl_xor_sync(0xffffffffu, v, o);
    return v;
}
__device__ __forceinline__ float sigmoidf_(float x) {
    return 1.0f / (1.0f + expf(-x));
}

// Single-stage grid barrier: every CTA bumps its flag, every CTA's warp 0
// polls all 128 flags directly (one L2 round trip on the critical path).
// Monotonic counters survive graph replays: all flags are equal at launch
// start, and `base` is captured before any flag can change.
__device__ __forceinline__ void grid_bar(int bid, unsigned base, unsigned* kbar) {
    unsigned k = ++(*kbar);
    __threadfence();              // release: prior global writes visible
    __syncthreads();
    if (threadIdx.x == 0) *(volatile unsigned*)&g_arrive[bid] = base + k;
    if (threadIdx.x < 32) {
        for (;;) {
            unsigned mn = 0xFFFFFFFFu;
#pragma unroll
            for (int i = 0; i < 4; i++) {
                unsigned d = (*(volatile unsigned*)&g_arrive[threadIdx.x + i * 32]) - base;
                mn = mn < d ? mn : d;
            }
            if (__all_sync(0xffffffffu, mn >= k)) break;
        }
    }
    __syncthreads();
    __threadfence();              // acquire side
}

// Load hidden state (fp32 global, other SMs' writes) -> SMEM as half2.
// 2048 floats, 512 threads: 4 floats (= 2 half2) per thread.
__device__ __forceinline__ void load_h_h2(const float* hsrc, __half2* hp, int tid) {
    float4 a = __ldcg((const float4*)(hsrc + tid * 4));
    uint2 u;
    *(__half2*)&u.x = __floats2half2_rn(a.x, a.y);
    *(__half2*)&u.y = __floats2half2_rn(a.z, a.w);
    *(uint2*)(hp + tid * 2) = u;
}

// Load hidden state into SMEM as fp32 (decoder logits path).
__device__ __forceinline__ void load_h_f32(const float* hsrc, float* hs, int tid) {
    float4 v = __ldcg((const float4*)(hsrc + tid * 4));
    *(float4*)&hs[tid * 4] = v;
}

// One-time: load this CTA's 48 Whh rows (fp32, global) into SMEM as fp16.
// SMEM row r48 = gate*16 + j  <->  global row gate*HID + bid*16 + j.
// 16 warps x 3 rows.
__device__ void load_w48(const float* __restrict__ W, __half* ws, int bid, int tid) {
    int warp = tid >> 5, lane = tid & 31;
#pragma unroll
    for (int rr = 0; rr < RPW; rr++) {
        int r48  = warp * RPW + rr;
        int grow = (r48 >> 4) * HID + bid * UPB + (r48 & 15);
        const float4* src = (const float4*)(W + (size_t)grow * HID);
#pragma unroll
        for (int c = 0; c < 16; c++) {
            float4 v = __ldg(&src[lane + c * 32]);
            union { __half2 h[2]; uint2 u; } cv;
            cv.h[0] = __floats2half2_rn(v.x, v.y);
            cv.h[1] = __floats2half2_rn(v.z, v.w);
            *(uint2*)&ws[(size_t)r48 * HID + (lane + c * 32) * 4] = cv.u;
        }
    }
}

// 48-row x 2048 matvec, fp16 weights+h in SMEM, HFMA2 inner product with
// fp32 flush every 16 elements. Warp w: rows w*3..w*3+2 -> gh_s[48]+bhh.
__device__ __forceinline__ void matvec48_h2(const __half* __restrict__ ws,
                                            const __half2* __restrict__ hp,
                                            float* gh_s, const float* bhh_s,
                                            int tid) {
    int warp = tid >> 5, lane = tid & 31;
    float acc[RPW] = {0.f, 0.f, 0.f};
#pragma unroll
    for (int c = 0; c < 8; c += 2) {
        int g0 = (c * 32 + lane) * 4;          // half2 index
        int g1 = ((c + 1) * 32 + lane) * 4;
        uint4 hu0 = *(const uint4*)(hp + g0);
        uint4 hu1 = *(const uint4*)(hp + g1);
        __half2 h0 = *(__half2*)&hu0.x, h1 = *(__half2*)&hu0.y;
        __half2 h2 = *(__half2*)&hu0.z, h3 = *(__half2*)&hu0.w;
        __half2 h4 = *(__half2*)&hu1.x, h5 = *(__half2*)&hu1.y;
        __half2 h6 = *(__half2*)&hu1.z, h7 = *(__half2*)&hu1.w;
#pragma unroll
        for (int rr = 0; rr < RPW; rr++) {
            const __half2* wrow =
                (const __half2*)(ws + (size_t)(warp * RPW + rr) * HID);
            uint4 w0 = *(const uint4*)(wrow + g0);
            uint4 w1 = *(const uint4*)(wrow + g1);
            __half2 s = __hmul2(*(__half2*)&w0.x, h0);
            s = __hfma2(*(__half2*)&w0.y, h1, s);
            s = __hfma2(*(__half2*)&w0.z, h2, s);
            s = __hfma2(*(__half2*)&w0.w, h3, s);
            s = __hfma2(*(__half2*)&w1.x, h4, s);
            s = __hfma2(*(__half2*)&w1.y, h5, s);
            s = __hfma2(*(__half2*)&w1.z, h6, s);
            s = __hfma2(*(__half2*)&w1.w, h7, s);
            float2 f = __half22float2(s);
            acc[rr] += f.x + f.y;
        }
    }
#pragma unroll
    for (int rr = 0; rr < RPW; rr++) {
        float s = warp_sum(acc[rr]);
        if (lane == 0) gh_s[warp * RPW + rr] = s + bhh_s[warp * RPW + rr];
    }
}

// ---------------- fp32 -> fp16 converters -----------------------------------
__global__ void __launch_bounds__(256) conv_x_kernel(const float* __restrict__ src) {
    int i = blockIdx.x * blockDim.x + threadIdx.x;   // float4 index
    if (i < SEQ * INSZ / 4) {
        float4 v = __ldg((const float4*)src + i);
        union { __half2 h[2]; uint2 u; } cv;
        cv.h[0] = __floats2half2_rn(v.x, v.y);
        cv.h[1] = __floats2half2_rn(v.z, v.w);
        ((uint2*)g_Xh)[i] = cv.u;
    }
}
__global__ void __launch_bounds__(256) conv_w_kernel(const float* __restrict__ src) {
    int i = blockIdx.x * blockDim.x + threadIdx.x;
    if (i < G3 * INSZ / 4) {
        float4 v = __ldg((const float4*)src + i);
        union { __half2 h[2]; uint2 u; } cv;
        cv.h[0] = __floats2half2_rn(v.x, v.y);
        cv.h[1] = __floats2half2_rn(v.z, v.w);
        ((uint2*)g_Wh)[i] = cv.u;
    }
}

// ---------------- kernel 1: GI = X @ Wih^T (tensor cores, fp32 accum) -------
// C[m,n] = sum_k Xh[m,k] * Wh[n,k];  M=512, N=6144, K=4096
#define KC 32
__global__ void __launch_bounds__(256) gemm_wmma_kernel() {
    __shared__ __half As[128][KC + 8];   // +8 halfs pad: ldm=40
    __shared__ __half Bs[128][KC + 8];

    int m0 = blockIdx.y * 128, n0 = blockIdx.x * 128;
    int t = threadIdx.x;
    int wid = t >> 5;
    int wm = wid & 1, wn = wid >> 1;     // warp tile: 64(M) x 32(N)

    wmma::fragment<wmma::accumulator, 16, 16, 16, float> c[4][2];
#pragma unroll
    for (int i = 0; i < 4; i++)
#pragma unroll
        for (int j = 0; j < 2; j++) wmma::fill_fragment(c[i][j], 0.f);

    int lrow = t >> 1;
    int lseg = (t & 1) * 16;             // half offset within KC

    for (int k0 = 0; k0 < INSZ; k0 += KC) {
        const uint4* ap = (const uint4*)(g_Xh + (size_t)(m0 + lrow) * INSZ + k0 + lseg);
        const uint4* bp = (const uint4*)(g_Wh + (size_t)(n0 + lrow) * INSZ + k0 + lseg);
        uint4 a0 = ap[0], a1 = ap[1];
        uint4 b0 = bp[0], b1 = bp[1];
        __syncthreads();
        *(uint4*)&As[lrow][lseg]     = a0;
        *(uint4*)&As[lrow][lseg + 8] = a1;
        *(uint4*)&Bs[lrow][lseg]     = b0;
        *(uint4*)&Bs[lrow][lseg + 8] = b1;
        __syncthreads();
#pragma unroll
        for (int kk = 0; kk < KC; kk += 16) {
            wmma::fragment<wmma::matrix_a, 16, 16, 16, __half, wmma::row_major> af[4];
            wmma::fragment<wmma::matrix_b, 16, 16, 16, __half, wmma::col_major> bf[2];
#pragma unroll
            for (int i = 0; i < 4; i++)
                wmma::load_matrix_sync(af[i], &As[wm * 64 + i * 16][kk], KC + 8);
#pragma unroll
            for (int j = 0; j < 2; j++)
                wmma::load_matrix_sync(bf[j], &Bs[wn * 32 + j * 16][kk], KC + 8);
#pragma unroll
            for (int i = 0; i < 4; i++)
#pragma unroll
                for (int j = 0; j < 2; j++)
                    wmma::mma_sync(c[i][j], af[i], bf[j], c[i][j]);
        }
    }
#pragma unroll
    for (int i = 0; i < 4; i++)
#pragma unroll
        for (int j = 0; j < 2; j++)
            wmma::store_matrix_sync(
                &g_GI[(size_t)(m0 + wm * 64 + i * 16) * G3 + n0 + wn * 32 + j * 16],
                c[i][j], G3, wmma::mem_row_major);
}

// ---------------- kernel 2: persistent encoder + decoder --------------------
__global__ void __launch_bounds__(NT, 1) rnn_kernel(
    const float* __restrict__ enc_Whh, const float* __restrict__ enc_bih,
    const float* __restrict__ enc_bhh,
    const float* __restrict__ dec_Wih, const float* __restrict__ dec_Whh,
    const float* __restrict__ dec_bih, const float* __restrict__ dec_bhh,
    const float* __restrict__ W_out,   const float* __restrict__ b_out,
    float* __restrict__ out) {

    extern __shared__ char dyn[];
    __half*  ws   = (__half*)dyn;                       // 48*2048 fp16 = 192KB
    __half2* hph2 = (__half2*)(dyn + RPB * HID * sizeof(__half));       // 4KB
    float*   hs32 = (float*)(dyn + RPB * HID * sizeof(__half)
                                 + HID * sizeof(__half));               // 8KB

    __shared__ float gh_s[RPB];
    __shared__ float gi_s[RPB];
    __shared__ float bhh_s[RPB];
    __shared__ float bih_s[RPB];
    __shared__ float ls[ORPB];

    int bid = blockIdx.x, tid = threadIdx.x;
    unsigned base = *(volatile unsigned*)&g_arrive[bid];  // stable at launch
    unsigned kbar = 0;

    // one-time: encoder Whh slice -> SMEM fp16; biases -> SMEM
    load_w48(enc_Whh, ws, bid, tid);
    if (tid < RPB) {
        int grow = (tid >> 4) * HID + bid * UPB + (tid & 15);
        bhh_s[tid] = enc_bhh[grow];
        bih_s[tid] = enc_bih[grow];
    }

    // per-launch re-init
    if (tid < UPB) __stcg(&g_h[0][bid * UPB + tid], 0.f);
    if (bid == 0 && tid < STEPS) {
        g_amax[tid]   = 0ull;
        g_sumexp[tid] = 0.f;
    }
    grid_bar(bid, base, &kbar);

    int cur = 0;

    // ---------------- encoder: 512 sequential GRU steps ----------------
    for (int t = 0; t < SEQ; t++) {
        load_h_h2(g_h[cur], hph2, tid);
        __syncthreads();
        matvec48_h2(ws, hph2, gh_s, bhh_s, tid);
        __syncthreads();
        if (tid < UPB) {
            int u = bid * UPB + tid;
            float hprev = __ldcg(&g_h[cur][u]);
            const float* gi = g_GI + (size_t)t * G3;
            float r = sigmoidf_(gi[u]           + bih_s[tid]       + gh_s[tid]);
            float z = sigmoidf_(gi[HID + u]     + bih_s[UPB + tid] + gh_s[UPB + tid]);
            float n = tanhf(    gi[2 * HID + u] + bih_s[2 * UPB + tid]
                                                + r * gh_s[2 * UPB + tid]);
            __stcg(&g_h[cur ^ 1][u], (1.f - z) * n + z * hprev);
        }
        cur ^= 1;
        grid_bar(bid, base, &kbar);
    }

    // ---------------- decoder: swap SMEM weights to dec_Whh ----------------
    load_w48(dec_Whh, ws, bid, tid);
    if (tid < RPB) {
        int grow = (tid >> 4) * HID + bid * UPB + (tid & 15);
        bhh_s[tid] = dec_bhh[grow];
    }
    __syncthreads();

    int prev_idx = -1;     // first x is the zero vector
    for (int s = 0; s < STEPS; s++) {
        load_h_h2(g_h[cur], hph2, tid);
        if (tid < RPB) {                       // gi = Wih[:,onehot] + bih
            int grow = (tid >> 4) * HID + bid * UPB + (tid & 15);
            float v = dec_bih[grow];
            if (prev_idx >= 0) v += __ldg(&dec_Wih[(size_t)grow * INSZ + prev_idx]);
            gi_s[tid] = v;
        }
        __syncthreads();
        matvec48_h2(ws, hph2, gh_s, bhh_s, tid);
        __syncthreads();
        if (tid < UPB) {
            int u = bid * UPB + tid;
            float hprev = __ldcg(&g_h[cur][u]);
            float r = sigmoidf_(gi_s[tid]           + gh_s[tid]);
            float z = sigmoidf_(gi_s[UPB + tid]     + gh_s[UPB + tid]);
            float n = tanhf(    gi_s[2 * UPB + tid] + r * gh_s[2 * UPB + tid]);
            __stcg(&g_h[cur ^ 1][u], (1.f - z) * n + z * hprev);
        }
        cur ^= 1;
        grid_bar(bid, base, &kbar);           // B1: h_new visible everywhere

        // logits for this CTA's 32 output rows (fp32, streamed from L2)
        load_h_f32(g_h[cur], hs32, tid);
        __syncthreads();
        {
            int warp = tid >> 5, lane = tid & 31;
#pragma unroll
            for (int rr = 0; rr < ORPW; rr++) {
                int rl = warp * ORPW + rr;
                int grow = bid * ORPB + rl;
                const float4* wrow = (const float4*)(W_out + (size_t)grow * HID);
                float acc = 0.f;
#pragma unroll
                for (int kk = 0; kk < 16; kk++) {
                    float4 w4 = __ldg(&wrow[lane + kk * 32]);
                    const float4 h4 = *(const float4*)&hs32[(lane + kk * 32) * 4];
                    acc += w4.x * h4.x + w4.y * h4.y + w4.z * h4.z + w4.w * h4.w;
                }
                acc = warp_sum(acc);
                if (lane == 0) ls[rl] = acc + b_out[grow];
            }
        }
        __syncthreads();

        // global (max, argmax) via packed atomicMax; first-index tie-break
        if (tid < 32) {
            float v = ls[tid];
            unsigned sb = __float_as_uint(v);
            sb = (sb & 0x80000000u) ? ~sb : (sb | 0x80000000u);
            unsigned long long pack =
                ((unsigned long long)sb << 32) |
                (unsigned long long)(0xFFFFFFFFu - (unsigned)(bid * ORPB + tid));
#pragma unroll
            for (int o = 16; o; o >>= 1) {
                unsigned long long other = __shfl_xor_sync(0xffffffffu, pack, o);
                pack = other > pack ? other : pack;
            }
            if (tid == 0) atomicMax(&g_amax[s], pack);
        }
        grid_bar(bid, base, &kbar);           // B2: global max ready

        unsigned long long pk = *(volatile unsigned long long*)&g_amax[s];
        unsigned hi = (unsigned)(pk >> 32);
        float gmax = __uint_as_float((hi & 0x80000000u) ? (hi & 0x7FFFFFFFu) : ~hi);

        if (tid < 32) {
            float e = expf(ls[tid] - gmax);
            e = warp_sum(e);
            if (tid == 0) atomicAdd(&g_sumexp[s], e);
        }
        grid_bar(bid, base, &kbar);           // B3: global sumexp ready

        float lse = logf(*(volatile float*)&g_sumexp[s]);
        if (tid < 32)
            out[(size_t)s * OUTSZ + bid * ORPB + tid] = ls[tid] - gmax - lse;
        prev_idx = (int)(0xFFFFFFFFu - (unsigned)(pk & 0xFFFFFFFFull));
    }
}

// ---------------- launch ----------------------------------------------------
extern "C" void kernel_launch(void* const* d_in, const int* in_sizes, int n_in,
                              void* d_out, int out_size) {
    const float* input   = (const float*)d_in[0];
    const float* enc_Wih = (const float*)d_in[1];
    const float* enc_Whh = (const float*)d_in[2];
    const float* enc_bih = (const float*)d_in[3];
    const float* enc_bhh = (const float*)d_in[4];
    const float* dec_Wih = (const float*)d_in[5];
    const float* dec_Whh = (const float*)d_in[6];
    const float* dec_bih = (const float*)d_in[7];
    const float* dec_bhh = (const float*)d_in[8];
    const float* W_out   = (const float*)d_in[9];
    const float* b_out   = (const float*)d_in[10];
    float* out = (float*)d_out;

    static const int kDynSmem = RPB * HID * sizeof(__half)      // weights 192KB
                              + HID * sizeof(__half)            // h fp16   4KB
                              + HID * sizeof(float);            // h fp32   8KB
    cudaFuncSetAttribute(rnn_kernel,
                         cudaFuncAttributeMaxDynamicSharedMemorySize, kDynSmem);

    conv_x_kernel<<<(SEQ * INSZ / 4 + 255) / 256, 256>>>(input);
    conv_w_kernel<<<(G3 * INSZ / 4 + 255) / 256, 256>>>(enc_Wih);

    dim3 g1(G3 / 128, SEQ / 128);   // 48 x 4
    gemm_wmma_kernel<<<g1, 256>>>();

    rnn_kernel<<<NB, NT, kDynSmem>>>(enc_Whh, enc_bih, enc_bhh,
                                     dec_Wih, dec_Whh, dec_bih, dec_bhh,
                                     W_out, b_out, out);
}